// round 4
// baseline (speedup 1.0000x reference)
#include <cuda_runtime.h>
#include <cstdint>

#define Zdim 41
#define Ydim 1024
#define Xdim 1024
#define NVOX (Zdim * Ydim * Xdim)      // 42,991,616
#define NWORDS (NVOX / 32)             // 1,343,488
#define C_IN 32
#define C_OUT 64
#define KVOL 27
#define KCENTER 13
#define MAXN 300000

// Dense index grid: validity gated by g_bitmap (wiped each launch), so the
// grid itself is never cleared and stale entries are never read.
__device__ int      g_grid[NVOX];
__device__ unsigned g_bitmap[NWORDS];
__device__ int      g_npairs;
__device__ int2     g_pairs[MAXN * (KVOL - 1)];   // (i<<5|k, nb)

__global__ void clear_bitmap_kernel() {
    int i = blockIdx.x * blockDim.x + threadIdx.x;
    if (i == 0) g_npairs = 0;
    if (i * 4 < NWORDS) ((uint4*)g_bitmap)[i] = make_uint4(0, 0, 0, 0);
}

__global__ void scatter_kernel(const int* __restrict__ idx, int n) {
    int i = blockIdx.x * blockDim.x + threadIdx.x;
    if (i >= n) return;
    int4 v = ((const int4*)idx)[i];
    unsigned lin = (unsigned)v.y * (Ydim * Xdim) + (unsigned)v.z * Xdim + (unsigned)v.w;
    g_grid[lin] = i;
    atomicOr(&g_bitmap[lin >> 5], 1u << (lin & 31));
}

// One thread per (point, offset): fully parallel probing, no dependency chains.
__global__ void probe_kernel(const int* __restrict__ idx, int n) {
    int t = blockIdx.x * blockDim.x + threadIdx.x;
    if (t >= n * KVOL) return;
    int i = t / KVOL;
    int k = t - i * KVOL;
    if (k == KCENTER) return;
    int4 v = ((const int4*)idx)[i];            // 27 threads share this line
    int nz = v.y + k / 9 - 1;
    int ny = v.z + (k / 3) % 3 - 1;
    int nx = v.w + k % 3 - 1;
    if ((unsigned)nz >= Zdim || (unsigned)ny >= Ydim || (unsigned)nx >= Xdim) return;
    unsigned lin = (unsigned)nz * (Ydim * Xdim) + (unsigned)ny * Xdim + (unsigned)nx;
    if (!((g_bitmap[lin >> 5] >> (lin & 31)) & 1u)) return;
    int nb = g_grid[lin];                      // rare (~0.7% of probes)
    int pos = atomicAdd(&g_npairs, 1);
    g_pairs[pos] = make_int2((i << 5) | k, nb);
}

// Packed fp32x2 FMA (ptxas never fuses this from C++).
__device__ __forceinline__ void fma2(unsigned long long& acc, float f,
                                     unsigned long long wv) {
    unsigned long long fv2;
    asm("mov.b64 %0, {%1, %1};" : "=l"(fv2) : "f"(f));
    asm("fma.rn.f32x2 %0, %1, %2, %3;" : "=l"(acc) : "l"(fv2), "l"(wv), "l"(acc));
}

// Center contribution: out[i] = feat[i] @ W13. Dense, no lookups.
// Weights in smem packed as float2(w[cout], w[cout+32]) per (cout,cin);
// row stride 34 float2 = 272 B (16B-aligned, conflict-free for LDS.128).
__global__ void __launch_bounds__(256) center_kernel(
    const float* __restrict__ feat,
    const float* __restrict__ w,
    float* __restrict__ out,
    int n)
{
    __shared__ float2 ws2[32][34];
    __shared__ float  sf[8][C_IN];

    const float* w13 = w + KCENTER * C_IN * C_OUT;
    for (int e = threadIdx.x; e < C_IN * 32; e += blockDim.x) {
        int cin = e >> 5, cl = e & 31;
        ws2[cl][cin] = make_float2(w13[cin * C_OUT + cl], w13[cin * C_OUT + cl + 32]);
    }
    __syncthreads();

    int lane   = threadIdx.x & 31;
    int wslot  = threadIdx.x >> 5;
    int warp_g = (blockIdx.x * blockDim.x + threadIdx.x) >> 5;
    int nwarps = (gridDim.x * blockDim.x) >> 5;

    const ulonglong2* wrow = (const ulonglong2*)&ws2[lane][0];

    for (int i = warp_g; i < n; i += nwarps) {
        sf[wslot][lane] = feat[(size_t)i * C_IN + lane];
        __syncwarp();

        unsigned long long acc;
        asm("mov.b64 %0, {%1, %1};" : "=l"(acc) : "f"(0.0f));

        const float4* fs = (const float4*)sf[wslot];
        #pragma unroll
        for (int c4 = 0; c4 < C_IN / 4; ++c4) {
            float4 fv = fs[c4];
            ulonglong2 q0 = wrow[c4 * 2];       // cin 4c4, 4c4+1
            ulonglong2 q1 = wrow[c4 * 2 + 1];   // cin 4c4+2, 4c4+3
            fma2(acc, fv.x, q0.x);
            fma2(acc, fv.y, q0.y);
            fma2(acc, fv.z, q1.x);
            fma2(acc, fv.w, q1.y);
        }
        __syncwarp();

        float o0, o1;
        asm("mov.b64 {%0, %1}, %2;" : "=f"(o0), "=f"(o1) : "l"(acc));
        out[(size_t)i * C_OUT + lane]      = o0;
        out[(size_t)i * C_OUT + lane + 32] = o1;
    }
}

// Rare neighbor contributions: persistent warps over the pair list,
// atomicAdd accumulation on top of the center result.
__global__ void __launch_bounds__(256) pairs_kernel(
    const float* __restrict__ feat,
    const float* __restrict__ w,
    float* __restrict__ out)
{
    int lane   = threadIdx.x & 31;
    int warp_g = (blockIdx.x * blockDim.x + threadIdx.x) >> 5;
    int nwarps = (gridDim.x * blockDim.x) >> 5;
    int np = g_npairs;

    for (int p = warp_g; p < np; p += nwarps) {
        int2 pr = g_pairs[p];
        int i  = pr.x >> 5;
        int k  = pr.x & 31;
        int nb = pr.y;

        float f = feat[(size_t)nb * C_IN + lane];   // coalesced 128 B row
        const float* wk = w + (size_t)k * C_IN * C_OUT;

        float a0 = 0.0f, a1 = 0.0f;
        #pragma unroll
        for (int c = 0; c < C_IN; ++c) {
            float fv = __shfl_sync(0xffffffffu, f, c);
            a0 += fv * wk[c * C_OUT + lane];
            a1 += fv * wk[c * C_OUT + lane + 32];
        }
        atomicAdd(&out[(size_t)i * C_OUT + lane],      a0);
        atomicAdd(&out[(size_t)i * C_OUT + lane + 32], a1);
    }
}

extern "C" void kernel_launch(void* const* d_in, const int* in_sizes, int n_in,
                              void* d_out, int out_size) {
    const float* feat = (const float*)d_in[0];
    const int*   idx  = (const int*)d_in[1];
    const float* w    = (const float*)d_in[2];
    float* out = (float*)d_out;

    int n = in_sizes[0] / C_IN;

    clear_bitmap_kernel<<<(NWORDS / 4 + 255) / 256, 256>>>();
    scatter_kernel<<<(n + 255) / 256, 256>>>(idx, n);
    probe_kernel<<<(n * KVOL + 255) / 256, 256>>>(idx, n);
    center_kernel<<<1184, 256>>>(feat, w, out, n);
    pairs_kernel<<<1184, 256>>>(feat, w, out);
}